// round 1
// baseline (speedup 1.0000x reference)
#include <cuda_runtime.h>
#include <math.h>

#define T_TOK 2048
#define DHID  1024
#define FINT  1408
#define NEXP  8

// ---- device scratch (no allocations allowed) ----
__device__ int            g_count[NEXP];
__device__ int            g_tok[NEXP * T_TOK];
__device__ float          g_wt [NEXP * T_TOK];
__device__ unsigned char  g_kslot[NEXP * T_TOK];
__device__ float          g_h[(size_t)NEXP * T_TOK * FINT];   // gated intermediate, per expert slot
__device__ float          g_y[(size_t)T_TOK * 2 * DHID];      // per (token, k) down-proj output

// ---------------------------------------------------------------------------
__global__ void zero_counts_kernel() {
    if (threadIdx.x < NEXP) g_count[threadIdx.x] = 0;
}

// One warp per token: logits, softmax, top-2, renorm, bucket into expert lists.
__global__ void router_kernel(const float* __restrict__ x,
                              const float* __restrict__ rw) {
    int warp = (blockIdx.x * blockDim.x + threadIdx.x) >> 5;
    int lane = threadIdx.x & 31;
    if (warp >= T_TOK) return;
    const float* xt = x + (size_t)warp * DHID;

    float logit[NEXP];
#pragma unroll
    for (int e = 0; e < NEXP; e++) {
        const float* w = rw + (size_t)e * DHID;
        float s = 0.f;
        for (int i = lane; i < DHID; i += 32) s += xt[i] * w[i];
#pragma unroll
        for (int o = 16; o > 0; o >>= 1) s += __shfl_xor_sync(0xffffffffu, s, o);
        logit[e] = s;
    }
    if (lane == 0) {
        float m = logit[0];
#pragma unroll
        for (int e = 1; e < NEXP; e++) m = fmaxf(m, logit[e]);
        float p[NEXP];
#pragma unroll
        for (int e = 0; e < NEXP; e++) p[e] = expf(logit[e] - m);
        // top-2 (first index wins ties, matching lax.top_k)
        int i1 = 0; float v1 = p[0];
#pragma unroll
        for (int e = 1; e < NEXP; e++) if (p[e] > v1) { v1 = p[e]; i1 = e; }
        int i2 = -1; float v2 = -1.f;
#pragma unroll
        for (int e = 0; e < NEXP; e++) {
            if (e == i1) continue;
            if (p[e] > v2) { v2 = p[e]; i2 = e; }
        }
        float inv = 1.f / (v1 + v2);
        float w1 = v1 * inv, w2 = v2 * inv;

        int pos1 = atomicAdd(&g_count[i1], 1);
        g_tok[i1 * T_TOK + pos1] = warp;  g_wt[i1 * T_TOK + pos1] = w1;  g_kslot[i1 * T_TOK + pos1] = 0;
        int pos2 = atomicAdd(&g_count[i2], 1);
        g_tok[i2 * T_TOK + pos2] = warp;  g_wt[i2 * T_TOK + pos2] = w2;  g_kslot[i2 * T_TOK + pos2] = 1;
    }
}

// ---------------------------------------------------------------------------
// Pass A: h = silu(x@Wg) * (x@Wu) for routed tokens of expert e.
// Tile 64(m) x 64(n) x 16(k); 256 threads, 4x4 per thread, dual accumulators.
__global__ __launch_bounds__(256) void gu_kernel(const float* __restrict__ x,
                                                 const float* __restrict__ wg,
                                                 const float* __restrict__ wu) {
    int e   = blockIdx.z;
    int cnt = g_count[e];
    int m0  = blockIdx.y * 64;
    if (m0 >= cnt) return;
    int n0  = blockIdx.x * 64;

    __shared__ __align__(16) float sA [16][64];
    __shared__ __align__(16) float sBg[16][64];
    __shared__ __align__(16) float sBu[16][64];

    int tid = threadIdx.x;
    int tx = tid & 15, ty = tid >> 4;

    // gather token indices for the 4 A-load rows this thread touches (row = tid/4)
    int arow = tid >> 2;               // 0..63
    int akoff = (tid & 3) * 4;         // 0,4,8,12
    int tokA = (m0 + arow < cnt) ? g_tok[e * T_TOK + m0 + arow] : -1;

    int brow = tid >> 4;               // 0..15
    int bnoff = (tid & 15) * 4;        // 0..60

    float cg[4][4], cu[4][4];
#pragma unroll
    for (int i = 0; i < 4; i++)
#pragma unroll
        for (int j = 0; j < 4; j++) { cg[i][j] = 0.f; cu[i][j] = 0.f; }

    const size_t wg_base = (size_t)e * DHID * FINT;
    const size_t wu_base = wg_base;

    for (int k0 = 0; k0 < DHID; k0 += 16) {
        // load A (gathered x) -> sA[k][m]
        float4 va = make_float4(0.f, 0.f, 0.f, 0.f);
        if (tokA >= 0)
            va = *(const float4*)&x[(size_t)tokA * DHID + k0 + akoff];
        sA[akoff + 0][arow] = va.x;
        sA[akoff + 1][arow] = va.y;
        sA[akoff + 2][arow] = va.z;
        sA[akoff + 3][arow] = va.w;
        // load Bg/Bu -> sB[k][n]
        float4 vg = *(const float4*)&wg[wg_base + (size_t)(k0 + brow) * FINT + n0 + bnoff];
        float4 vu = *(const float4*)&wu[wu_base + (size_t)(k0 + brow) * FINT + n0 + bnoff];
        *(float4*)&sBg[brow][bnoff] = vg;
        *(float4*)&sBu[brow][bnoff] = vu;
        __syncthreads();

#pragma unroll
        for (int kk = 0; kk < 16; kk++) {
            float4 a  = *(const float4*)&sA [kk][ty * 4];
            float4 bg = *(const float4*)&sBg[kk][tx * 4];
            float4 bu = *(const float4*)&sBu[kk][tx * 4];
            float av[4] = {a.x, a.y, a.z, a.w};
            float gv[4] = {bg.x, bg.y, bg.z, bg.w};
            float uv[4] = {bu.x, bu.y, bu.z, bu.w};
#pragma unroll
            for (int i = 0; i < 4; i++)
#pragma unroll
                for (int j = 0; j < 4; j++) {
                    cg[i][j] += av[i] * gv[j];
                    cu[i][j] += av[i] * uv[j];
                }
        }
        __syncthreads();
    }

    // epilogue: h = silu(g) * u
#pragma unroll
    for (int i = 0; i < 4; i++) {
        int row = m0 + ty * 4 + i;
        if (row >= cnt) continue;
        float4 hv;
        float* hp = &hv.x;
#pragma unroll
        for (int j = 0; j < 4; j++) {
            float g = cg[i][j];
            float s = g / (1.f + expf(-g));
            hp[j] = s * cu[i][j];
        }
        *(float4*)&g_h[((size_t)e * T_TOK + row) * FINT + n0 + tx * 4] = hv;
    }
}

// ---------------------------------------------------------------------------
// Pass B: y = (h @ Wd) * routing_weight, scattered to per-(token,k) slots.
__global__ __launch_bounds__(256) void down_kernel(const float* __restrict__ wd) {
    int e   = blockIdx.z;
    int cnt = g_count[e];
    int m0  = blockIdx.y * 64;
    if (m0 >= cnt) return;
    int n0  = blockIdx.x * 64;

    __shared__ __align__(16) float sA[16][64];
    __shared__ __align__(16) float sB[16][64];

    int tid = threadIdx.x;
    int tx = tid & 15, ty = tid >> 4;

    int arow = tid >> 2;
    int akoff = (tid & 3) * 4;
    bool avalid = (m0 + arow < cnt);

    int brow = tid >> 4;
    int bnoff = (tid & 15) * 4;

    float c[4][4];
#pragma unroll
    for (int i = 0; i < 4; i++)
#pragma unroll
        for (int j = 0; j < 4; j++) c[i][j] = 0.f;

    const size_t wd_base = (size_t)e * FINT * DHID;
    const size_t h_base  = (size_t)e * T_TOK * FINT;

    for (int k0 = 0; k0 < FINT; k0 += 16) {
        float4 va = make_float4(0.f, 0.f, 0.f, 0.f);
        if (avalid)
            va = *(const float4*)&g_h[h_base + (size_t)(m0 + arow) * FINT + k0 + akoff];
        sA[akoff + 0][arow] = va.x;
        sA[akoff + 1][arow] = va.y;
        sA[akoff + 2][arow] = va.z;
        sA[akoff + 3][arow] = va.w;
        float4 vb = *(const float4*)&wd[wd_base + (size_t)(k0 + brow) * DHID + n0 + bnoff];
        *(float4*)&sB[brow][bnoff] = vb;
        __syncthreads();

#pragma unroll
        for (int kk = 0; kk < 16; kk++) {
            float4 a = *(const float4*)&sA[kk][ty * 4];
            float4 b = *(const float4*)&sB[kk][tx * 4];
            float av[4] = {a.x, a.y, a.z, a.w};
            float bv[4] = {b.x, b.y, b.z, b.w};
#pragma unroll
            for (int i = 0; i < 4; i++)
#pragma unroll
                for (int j = 0; j < 4; j++)
                    c[i][j] += av[i] * bv[j];
        }
        __syncthreads();
    }

#pragma unroll
    for (int i = 0; i < 4; i++) {
        int row = m0 + ty * 4 + i;
        if (row >= cnt) continue;
        int   tok = g_tok[e * T_TOK + row];
        float w   = g_wt[e * T_TOK + row];
        int   ks  = g_kslot[e * T_TOK + row];
        float4 yv;
        yv.x = c[i][0] * w; yv.y = c[i][1] * w; yv.z = c[i][2] * w; yv.w = c[i][3] * w;
        *(float4*)&g_y[((size_t)tok * 2 + ks) * DHID + n0 + tx * 4] = yv;
    }
}

// ---------------------------------------------------------------------------
__global__ void combine_kernel(float* __restrict__ out) {
    int i = blockIdx.x * blockDim.x + threadIdx.x;   // over T*D/4
    int t = i / (DHID / 4);
    int d4 = i % (DHID / 4);
    const float4 a = *(const float4*)&g_y[((size_t)t * 2 + 0) * DHID + d4 * 4];
    const float4 b = *(const float4*)&g_y[((size_t)t * 2 + 1) * DHID + d4 * 4];
    float4 o;
    o.x = a.x + b.x; o.y = a.y + b.y; o.z = a.z + b.z; o.w = a.w + b.w;
    *(float4*)&out[(size_t)t * DHID + d4 * 4] = o;
}

// ---------------------------------------------------------------------------
extern "C" void kernel_launch(void* const* d_in, const int* in_sizes, int n_in,
                              void* d_out, int out_size) {
    const float* x  = (const float*)d_in[0];   // [2,1024,1024]
    const float* rw = (const float*)d_in[1];   // [8,1024]
    const float* wg = (const float*)d_in[2];   // [8,1024,1408]
    const float* wu = (const float*)d_in[3];   // [8,1024,1408]
    const float* wd = (const float*)d_in[4];   // [8,1408,1024]
    float* out = (float*)d_out;

    zero_counts_kernel<<<1, 32>>>();
    router_kernel<<<T_TOK / 8, 256>>>(x, rw);
    gu_kernel<<<dim3(FINT / 64, T_TOK / 64, NEXP), 256>>>(x, wg, wu);
    down_kernel<<<dim3(DHID / 64, T_TOK / 64, NEXP), 256>>>(wd);
    combine_kernel<<<(T_TOK * DHID / 4) / 256, 256>>>(out);
}

// round 4
// speedup vs baseline: 1.8476x; 1.8476x over previous
#include <cuda_runtime.h>
#include <cuda_bf16.h>
#include <mma.h>
#include <math.h>
#include <stdint.h>

using namespace nvcuda;

#define T_TOK 2048
#define DHID  1024
#define FINT  1408
#define NEXP  8

// ---------------- device scratch (static: no allocations allowed) ----------
__device__ int            g_count[NEXP];
__device__ int            g_tok[NEXP * T_TOK];
__device__ float          g_wt [NEXP * T_TOK];
__device__ unsigned char  g_kslot[NEXP * T_TOK];

// gathered activations per (expert, slot), bf16 hi/lo split, K-major rows
__device__ __nv_bfloat16  g_xh[(size_t)NEXP * T_TOK * DHID];
__device__ __nv_bfloat16  g_xl[(size_t)NEXP * T_TOK * DHID];
// gated intermediate, bf16 hi/lo, K-major over FINT
__device__ __nv_bfloat16  g_hh[(size_t)NEXP * T_TOK * FINT];
__device__ __nv_bfloat16  g_hl[(size_t)NEXP * T_TOK * FINT];
// per (token, k) down-proj output
__device__ float          g_y[(size_t)T_TOK * 2 * DHID];

// ---------------- routing ---------------------------------------------------
__global__ void zero_counts_kernel() {
    if (threadIdx.x < NEXP) g_count[threadIdx.x] = 0;
}

__global__ void router_kernel(const float* __restrict__ x,
                              const float* __restrict__ rw) {
    int warp = (blockIdx.x * blockDim.x + threadIdx.x) >> 5;
    int lane = threadIdx.x & 31;
    if (warp >= T_TOK) return;
    const float* xt = x + (size_t)warp * DHID;

    float logit[NEXP];
#pragma unroll
    for (int e = 0; e < NEXP; e++) {
        const float* w = rw + (size_t)e * DHID;
        float s = 0.f;
        for (int i = lane; i < DHID; i += 32) s += xt[i] * w[i];
#pragma unroll
        for (int o = 16; o > 0; o >>= 1) s += __shfl_xor_sync(0xffffffffu, s, o);
        logit[e] = s;
    }
    if (lane == 0) {
        float m = logit[0];
#pragma unroll
        for (int e = 1; e < NEXP; e++) m = fmaxf(m, logit[e]);
        float p[NEXP];
#pragma unroll
        for (int e = 0; e < NEXP; e++) p[e] = expf(logit[e] - m);
        int i1 = 0; float v1 = p[0];
#pragma unroll
        for (int e = 1; e < NEXP; e++) if (p[e] > v1) { v1 = p[e]; i1 = e; }
        int i2 = -1; float v2 = -1.f;
#pragma unroll
        for (int e = 0; e < NEXP; e++) {
            if (e == i1) continue;
            if (p[e] > v2) { v2 = p[e]; i2 = e; }
        }
        float inv = 1.f / (v1 + v2);
        int pos1 = atomicAdd(&g_count[i1], 1);
        g_tok[i1 * T_TOK + pos1] = warp;  g_wt[i1 * T_TOK + pos1] = v1 * inv;  g_kslot[i1 * T_TOK + pos1] = 0;
        int pos2 = atomicAdd(&g_count[i2], 1);
        g_tok[i2 * T_TOK + pos2] = warp;  g_wt[i2 * T_TOK + pos2] = v2 * inv;  g_kslot[i2 * T_TOK + pos2] = 1;
    }
}

// gather routed tokens into per-expert contiguous bf16 hi/lo rows
__global__ void gather_x_kernel(const float* __restrict__ x) {
    int s = blockIdx.x, e = blockIdx.y;
    if (s >= g_count[e]) return;
    int t = g_tok[e * T_TOK + s];
    const float* src = x + (size_t)t * DHID;
    size_t dst = ((size_t)e * T_TOK + s) * DHID;
    for (int i = threadIdx.x; i < DHID; i += 128) {
        float v = src[i];
        __nv_bfloat16 hi = __float2bfloat16(v);
        __nv_bfloat16 lo = __float2bfloat16(v - __bfloat162float(hi));
        g_xh[dst + i] = hi;
        g_xl[dst + i] = lo;
    }
}

// ---------------- gate+up WMMA GEMM with fused SwiGLU epilogue -------------
// Block tile: 128(m) x 64(n), both gate & up B tiles. 8 warps = 4(m) x 2(n),
// warp tile 32x32 per matrix. K-tile 32 (2 wmma k-steps).
__global__ void __launch_bounds__(256) gu_wmma_kernel(const float* __restrict__ wg,
                                                      const float* __restrict__ wu) {
    int e   = blockIdx.z;
    int cnt = g_count[e];
    int m0  = blockIdx.y * 128;
    if (m0 >= cnt) return;
    int n0  = blockIdx.x * 64;

    __shared__ union {
        struct {
            __nv_bfloat16 Ah[128][40];
            __nv_bfloat16 Al[128][40];
            __nv_bfloat16 Bh[2][32][72];
            __nv_bfloat16 Bl[2][32][72];
        } ld;
        float ebuf[8][32 * 36];           // ldm 36: multiple of 4 floats (16B)
    } sm;

    int tid = threadIdx.x, wid = tid >> 5, lane = tid & 31;
    int wm = wid & 3, wn = wid >> 2;

    const float* W[2];
    W[0] = wg + (size_t)e * DHID * FINT + n0;
    W[1] = wu + (size_t)e * DHID * FINT + n0;
    size_t aBase = (size_t)e * T_TOK + m0;

    wmma::fragment<wmma::accumulator, 16, 16, 16, float> c[2][2][2];
#pragma unroll
    for (int mat = 0; mat < 2; mat++)
#pragma unroll
        for (int mf = 0; mf < 2; mf++)
#pragma unroll
            for (int nf = 0; nf < 2; nf++)
                wmma::fill_fragment(c[mat][mf][nf], 0.0f);

    for (int k0 = 0; k0 < DHID; k0 += 32) {
        __syncthreads();
        // A: 128 rows x 32 k bf16 (hi & lo), 512 float4 each -> 2 per thread
#pragma unroll
        for (int i = 0; i < 2; i++) {
            int idx = tid + i * 256;
            int r = idx >> 2, cc = idx & 3;
            size_t off = (aBase + r) * DHID + k0 + cc * 8;
            *(float4*)&sm.ld.Ah[r][cc * 8] = *(const float4*)(g_xh + off);
            *(float4*)&sm.ld.Al[r][cc * 8] = *(const float4*)(g_xl + off);
        }
        // B: 2 mats x 32 rows x 64 floats = 1024 float4 -> 4 per thread
#pragma unroll
        for (int i = 0; i < 4; i++) {
            int idx = tid + i * 256;
            int mat = idx >> 9;
            int rem = idx & 511;
            int kk = rem >> 4, cc = rem & 15;
            float4 v = *(const float4*)&W[mat][(size_t)(k0 + kk) * FINT + cc * 4];
            __nv_bfloat16 hx = __float2bfloat16(v.x);
            __nv_bfloat16 hy = __float2bfloat16(v.y);
            __nv_bfloat16 hz = __float2bfloat16(v.z);
            __nv_bfloat16 hw = __float2bfloat16(v.w);
            __nv_bfloat162 h01; h01.x = hx; h01.y = hy;
            __nv_bfloat162 h23; h23.x = hz; h23.y = hw;
            __nv_bfloat162 l01, l23;
            l01.x = __float2bfloat16(v.x - __bfloat162float(hx));
            l01.y = __float2bfloat16(v.y - __bfloat162float(hy));
            l23.x = __float2bfloat16(v.z - __bfloat162float(hz));
            l23.y = __float2bfloat16(v.w - __bfloat162float(hw));
            *(__nv_bfloat162*)&sm.ld.Bh[mat][kk][cc * 4 + 0] = h01;
            *(__nv_bfloat162*)&sm.ld.Bh[mat][kk][cc * 4 + 2] = h23;
            *(__nv_bfloat162*)&sm.ld.Bl[mat][kk][cc * 4 + 0] = l01;
            *(__nv_bfloat162*)&sm.ld.Bl[mat][kk][cc * 4 + 2] = l23;
        }
        __syncthreads();

#pragma unroll
        for (int kk16 = 0; kk16 < 32; kk16 += 16) {
            wmma::fragment<wmma::matrix_a, 16, 16, 16, __nv_bfloat16, wmma::row_major> ah[2], al[2];
#pragma unroll
            for (int mf = 0; mf < 2; mf++) {
                wmma::load_matrix_sync(ah[mf], &sm.ld.Ah[wm * 32 + mf * 16][kk16], 40);
                wmma::load_matrix_sync(al[mf], &sm.ld.Al[wm * 32 + mf * 16][kk16], 40);
            }
#pragma unroll
            for (int mat = 0; mat < 2; mat++) {
#pragma unroll
                for (int nf = 0; nf < 2; nf++) {
                    wmma::fragment<wmma::matrix_b, 16, 16, 16, __nv_bfloat16, wmma::row_major> bh, bl;
                    wmma::load_matrix_sync(bh, &sm.ld.Bh[mat][kk16][wn * 32 + nf * 16], 72);
                    wmma::load_matrix_sync(bl, &sm.ld.Bl[mat][kk16][wn * 32 + nf * 16], 72);
#pragma unroll
                    for (int mf = 0; mf < 2; mf++) {
                        wmma::mma_sync(c[mat][mf][nf], ah[mf], bh, c[mat][mf][nf]);
                        wmma::mma_sync(c[mat][mf][nf], ah[mf], bl, c[mat][mf][nf]);
                        wmma::mma_sync(c[mat][mf][nf], al[mf], bh, c[mat][mf][nf]);
                    }
                }
            }
        }
    }

    // ---- fused SwiGLU epilogue ----
    __syncthreads();   // done with load buffers; ebuf aliases them
    float* buf = sm.ebuf[wid];
    int grow = m0 + wm * 32 + lane;
    bool ok = grow < cnt;
    size_t hbase = ((size_t)e * T_TOK + grow) * FINT + n0 + wn * 32;

    // gate matrix -> buf -> regs
#pragma unroll
    for (int mf = 0; mf < 2; mf++)
#pragma unroll
        for (int nf = 0; nf < 2; nf++)
            wmma::store_matrix_sync(&buf[mf * 16 * 36 + nf * 16], c[0][mf][nf], 36, wmma::mem_row_major);
    __syncwarp();
    float gv[32];
#pragma unroll
    for (int j = 0; j < 32; j++) gv[j] = buf[lane * 36 + j];
    __syncwarp();
    // up matrix -> buf -> regs
#pragma unroll
    for (int mf = 0; mf < 2; mf++)
#pragma unroll
        for (int nf = 0; nf < 2; nf++)
            wmma::store_matrix_sync(&buf[mf * 16 * 36 + nf * 16], c[1][mf][nf], 36, wmma::mem_row_major);
    __syncwarp();
    if (ok) {
#pragma unroll
        for (int j = 0; j < 32; j += 2) {
            float u0 = buf[lane * 36 + j];
            float u1 = buf[lane * 36 + j + 1];
            float g0 = gv[j], g1 = gv[j + 1];
            float h0 = g0 / (1.f + expf(-g0)) * u0;
            float h1 = g1 / (1.f + expf(-g1)) * u1;
            __nv_bfloat16 h0h = __float2bfloat16(h0);
            __nv_bfloat16 h1h = __float2bfloat16(h1);
            __nv_bfloat162 vh; vh.x = h0h; vh.y = h1h;
            __nv_bfloat162 vl;
            vl.x = __float2bfloat16(h0 - __bfloat162float(h0h));
            vl.y = __float2bfloat16(h1 - __bfloat162float(h1h));
            *(__nv_bfloat162*)&g_hh[hbase + j] = vh;
            *(__nv_bfloat162*)&g_hl[hbase + j] = vl;
        }
    }
}

// ---------------- down WMMA GEMM with routing-weight epilogue --------------
// Block tile 128(m) x 128(n); 8 warps = 4(m) x 2(n); warp tile 32 x 64.
__global__ void __launch_bounds__(256) down_wmma_kernel(const float* __restrict__ wd) {
    int e   = blockIdx.z;
    int cnt = g_count[e];
    int m0  = blockIdx.y * 128;
    if (m0 >= cnt) return;
    int n0  = blockIdx.x * 128;

    __shared__ union {
        struct {
            __nv_bfloat16 Ah[128][40];
            __nv_bfloat16 Al[128][40];
            __nv_bfloat16 Bh[32][136];
            __nv_bfloat16 Bl[32][136];
        } ld;
        float ebuf[8][32 * 36];           // ldm 36: multiple of 4 floats (16B)
    } sm;

    int tid = threadIdx.x, wid = tid >> 5, lane = tid & 31;
    int wm = wid & 3, wn = wid >> 2;

    const float* W = wd + (size_t)e * FINT * DHID + n0;
    size_t aBase = (size_t)e * T_TOK + m0;

    wmma::fragment<wmma::accumulator, 16, 16, 16, float> c[2][4];
#pragma unroll
    for (int mf = 0; mf < 2; mf++)
#pragma unroll
        for (int nf = 0; nf < 4; nf++)
            wmma::fill_fragment(c[mf][nf], 0.0f);

    for (int k0 = 0; k0 < FINT; k0 += 32) {
        __syncthreads();
#pragma unroll
        for (int i = 0; i < 2; i++) {
            int idx = tid + i * 256;
            int r = idx >> 2, cc = idx & 3;
            size_t off = (aBase + r) * FINT + k0 + cc * 8;
            *(float4*)&sm.ld.Ah[r][cc * 8] = *(const float4*)(g_hh + off);
            *(float4*)&sm.ld.Al[r][cc * 8] = *(const float4*)(g_hl + off);
        }
        // B: 32 rows x 128 floats = 1024 float4 -> 4 per thread
#pragma unroll
        for (int i = 0; i < 4; i++) {
            int idx = tid + i * 256;
            int kk = idx >> 5, cc = idx & 31;
            float4 v = *(const float4*)&W[(size_t)(k0 + kk) * DHID + cc * 4];
            __nv_bfloat16 hx = __float2bfloat16(v.x);
            __nv_bfloat16 hy = __float2bfloat16(v.y);
            __nv_bfloat16 hz = __float2bfloat16(v.z);
            __nv_bfloat16 hw = __float2bfloat16(v.w);
            __nv_bfloat162 h01; h01.x = hx; h01.y = hy;
            __nv_bfloat162 h23; h23.x = hz; h23.y = hw;
            __nv_bfloat162 l01, l23;
            l01.x = __float2bfloat16(v.x - __bfloat162float(hx));
            l01.y = __float2bfloat16(v.y - __bfloat162float(hy));
            l23.x = __float2bfloat16(v.z - __bfloat162float(hz));
            l23.y = __float2bfloat16(v.w - __bfloat162float(hw));
            *(__nv_bfloat162*)&sm.ld.Bh[kk][cc * 4 + 0] = h01;
            *(__nv_bfloat162*)&sm.ld.Bh[kk][cc * 4 + 2] = h23;
            *(__nv_bfloat162*)&sm.ld.Bl[kk][cc * 4 + 0] = l01;
            *(__nv_bfloat162*)&sm.ld.Bl[kk][cc * 4 + 2] = l23;
        }
        __syncthreads();

#pragma unroll
        for (int kk16 = 0; kk16 < 32; kk16 += 16) {
            wmma::fragment<wmma::matrix_a, 16, 16, 16, __nv_bfloat16, wmma::row_major> ah[2], al[2];
#pragma unroll
            for (int mf = 0; mf < 2; mf++) {
                wmma::load_matrix_sync(ah[mf], &sm.ld.Ah[wm * 32 + mf * 16][kk16], 40);
                wmma::load_matrix_sync(al[mf], &sm.ld.Al[wm * 32 + mf * 16][kk16], 40);
            }
#pragma unroll
            for (int nf = 0; nf < 4; nf++) {
                wmma::fragment<wmma::matrix_b, 16, 16, 16, __nv_bfloat16, wmma::row_major> bh, bl;
                wmma::load_matrix_sync(bh, &sm.ld.Bh[kk16][wn * 64 + nf * 16], 136);
                wmma::load_matrix_sync(bl, &sm.ld.Bl[kk16][wn * 64 + nf * 16], 136);
#pragma unroll
                for (int mf = 0; mf < 2; mf++) {
                    wmma::mma_sync(c[mf][nf], ah[mf], bh, c[mf][nf]);
                    wmma::mma_sync(c[mf][nf], ah[mf], bl, c[mf][nf]);
                    wmma::mma_sync(c[mf][nf], al[mf], bh, c[mf][nf]);
                }
            }
        }
    }

    // ---- scaled scatter epilogue (two 32-col halves through smem) ----
    __syncthreads();
    float* buf = sm.ebuf[wid];
    int grow = m0 + wm * 32 + lane;
    bool ok = grow < cnt;
    int   tok = 0, ks = 0;
    float w = 0.f;
    if (ok) {
        tok = g_tok[e * T_TOK + grow];
        w   = g_wt [e * T_TOK + grow];
        ks  = g_kslot[e * T_TOK + grow];
    }
    size_t ybase = ((size_t)tok * 2 + ks) * DHID + n0 + wn * 64;

#pragma unroll
    for (int half = 0; half < 2; half++) {
        __syncwarp();
#pragma unroll
        for (int mf = 0; mf < 2; mf++)
#pragma unroll
            for (int nf = 0; nf < 2; nf++)
                wmma::store_matrix_sync(&buf[mf * 16 * 36 + nf * 16], c[mf][half * 2 + nf], 36, wmma::mem_row_major);
        __syncwarp();
        if (ok) {
#pragma unroll
            for (int j = 0; j < 32; j += 2) {
                float2 v;
                v.x = buf[lane * 36 + j]     * w;
                v.y = buf[lane * 36 + j + 1] * w;
                *(float2*)&g_y[ybase + half * 32 + j] = v;
            }
        }
    }
}

// ---------------- combine ---------------------------------------------------
__global__ void combine_kernel(float* __restrict__ out) {
    int i  = blockIdx.x * blockDim.x + threadIdx.x;
    int t  = i / (DHID / 4);
    int d4 = i % (DHID / 4);
    const float4 a = *(const float4*)&g_y[((size_t)t * 2 + 0) * DHID + d4 * 4];
    const float4 b = *(const float4*)&g_y[((size_t)t * 2 + 1) * DHID + d4 * 4];
    float4 o;
    o.x = a.x + b.x; o.y = a.y + b.y; o.z = a.z + b.z; o.w = a.w + b.w;
    *(float4*)&out[(size_t)t * DHID + d4 * 4] = o;
}

// ---------------- launch ----------------------------------------------------
extern "C" void kernel_launch(void* const* d_in, const int* in_sizes, int n_in,
                              void* d_out, int out_size) {
    const float* x  = (const float*)d_in[0];
    const float* rw = (const float*)d_in[1];
    const float* wg = (const float*)d_in[2];
    const float* wu = (const float*)d_in[3];
    const float* wd = (const float*)d_in[4];
    float* out = (float*)d_out;

    zero_counts_kernel<<<1, 32>>>();
    router_kernel<<<T_TOK / 8, 256>>>(x, rw);
    gather_x_kernel<<<dim3(T_TOK, NEXP), 128>>>(x);

    gu_wmma_kernel  <<<dim3(FINT / 64, T_TOK / 128, NEXP), 256>>>(wg, wu);
    down_wmma_kernel<<<dim3(DHID / 128, T_TOK / 128, NEXP), 256>>>(wd);

    combine_kernel<<<(T_TOK * DHID / 4) / 256, 256>>>(out);
}